// round 2
// baseline (speedup 1.0000x reference)
#include <cuda_runtime.h>
#include <cstdint>

#define TBK      128   // tokens per block
#define NTHREADS 256
#define HID      128
#define NEXP     64
#define TBKP     132   // xs row pad (floats): coalesced-LDG transpose, 2-way STS conflict
#define LPAD     68    // logits row pad (16B-aligned rows, conflict-free float4 reads)
#define NEGINF   (__int_as_float(0xff800000u))

// ---- device scratch ----
__device__ float              g_Wt[HID * NEXP];     // k-major transposed W
__device__ unsigned long long g_scoreFix[NEXP];     // fixed-point sum of softmax scores
__device__ int                g_cnt[NEXP];          // topk index counts

// ---- f32x2 helpers ----
__device__ __forceinline__ unsigned long long pack_dup(float v) {
    unsigned long long r;
    unsigned int b = __float_as_uint(v);
    asm("mov.b64 %0, {%1, %1};" : "=l"(r) : "r"(b));
    return r;
}
__device__ __forceinline__ void ffma2(unsigned long long& d, unsigned long long a,
                                      unsigned long long b) {
    asm("fma.rn.f32x2 %0, %1, %2, %0;" : "+l"(d) : "l"(a), "l"(b));
}
__device__ __forceinline__ void unpack2(unsigned long long v, float& lo, float& hi) {
    unsigned int a, b;
    asm("mov.b64 {%0, %1}, %2;" : "=r"(a), "=r"(b) : "l"(v));
    lo = __uint_as_float(a);
    hi = __uint_as_float(b);
}

// ---- tournament argmax over 32 register values, exact lower-index tie-break ----
__device__ __forceinline__ void argmax32(const float (&v)[32], unsigned mask,
                                         float& bv, int& bi) {
    float a[16]; int ia[16];
#pragma unroll
    for (int i = 0; i < 16; ++i) {
        float x0 = (mask & (1u << (2 * i)))     ? NEGINF : v[2 * i];
        float x1 = (mask & (1u << (2 * i + 1))) ? NEGINF : v[2 * i + 1];
        bool p = x0 >= x1;                // ties -> left (lower index)
        a[i]  = p ? x0 : x1;
        ia[i] = p ? 2 * i : 2 * i + 1;
    }
    float b[8]; int ib[8];
#pragma unroll
    for (int i = 0; i < 8; ++i) {
        bool p = a[2 * i] >= a[2 * i + 1];
        b[i]  = p ? a[2 * i] : a[2 * i + 1];
        ib[i] = p ? ia[2 * i] : ia[2 * i + 1];
    }
    float c[4]; int ic[4];
#pragma unroll
    for (int i = 0; i < 4; ++i) {
        bool p = b[2 * i] >= b[2 * i + 1];
        c[i]  = p ? b[2 * i] : b[2 * i + 1];
        ic[i] = p ? ib[2 * i] : ib[2 * i + 1];
    }
    float d0, d1; int id0, id1;
    {
        bool p0 = c[0] >= c[1];
        d0 = p0 ? c[0] : c[1];  id0 = p0 ? ic[0] : ic[1];
        bool p1 = c[2] >= c[3];
        d1 = p1 ? c[2] : c[3];  id1 = p1 ? ic[2] : ic[3];
    }
    bool p = d0 >= d1;
    bv = p ? d0 : d1;
    bi = p ? id0 : id1;
}

// ---- kernel 1: transpose W, zero accumulators ----
__global__ void moe_prep(const float* __restrict__ W) {
    int b = blockIdx.x;
    if (b == 32) {
        if (threadIdx.x < NEXP) {
            g_scoreFix[threadIdx.x] = 0ull;
            g_cnt[threadIdx.x]      = 0;
        }
        return;
    }
    int i = b * 256 + threadIdx.x;   // output index: g_Wt[k][e]
    int k = i >> 6;
    int e = i & 63;
    g_Wt[i] = W[e * HID + k];
}

// ---- kernel 2: fused gate ----
extern __shared__ float smem[];

__global__ __launch_bounds__(NTHREADS, 2)
void moe_main(const float* __restrict__ x, float* __restrict__ out, int N) {
    float* xs   = smem;                       // [HID][TBKP]  (x transposed)
    float* Ws   = smem + HID * TBKP;          // [HID][NEXP]  (W k-major)
    float* sc   = Ws + HID * NEXP;            // [TBK][2]     half-scales e^{mh-m}/Z
    int*   cntS = (int*)(sc + TBK * 2);       // [NEXP]
    float* L    = xs;                         // [TBK][LPAD]  logits->exps, aliases xs

    // aliases into Ws after the GEMM is done reading it:
    float* candV = Ws;                        // [TBK][12]
    int*   candI = (int*)(Ws + TBK * 12);     // [TBK][12]
    float* mzA   = Ws + TBK * 24;             // [TBK][4]: mA, ZA, mB, ZB
    float* part  = Ws + TBK * 28;             // [4][64] Pi partials

    const int tid = threadIdx.x;
    const long long blk = blockIdx.x;
    const float* xblk = x + blk * (long long)(TBK * HID);

    // --- stage x tile transposed: coalesced float4 LDG, strided STS ---
    {
        const float4* gx = reinterpret_cast<const float4*>(xblk);
#pragma unroll
        for (int c = 0; c < 16; ++c) {
            int f = c * NTHREADS + tid;       // float4 index over [TBK][HID/4]
            float4 g = gx[f];
            int t  = f >> 5;                  // token
            int k4 = (f & 31) * 4;            // hidden base
            xs[(k4 + 0) * TBKP + t] = g.x;
            xs[(k4 + 1) * TBKP + t] = g.y;
            xs[(k4 + 2) * TBKP + t] = g.z;
            xs[(k4 + 3) * TBKP + t] = g.w;
        }
    }
    for (int i = tid; i < HID * NEXP; i += NTHREADS) Ws[i] = g_Wt[i];
    if (tid < NEXP) cntS[tid] = 0;
    __syncthreads();

    // --- register-tiled GEMM: 4 tokens x 8 experts per thread, f32x2 over experts ---
    const int tx = tid & 31;
    const int ty = tid >> 5;
    unsigned long long acc[4][4];
#pragma unroll
    for (int r = 0; r < 4; ++r)
#pragma unroll
        for (int c = 0; c < 4; ++c) acc[r][c] = 0ull;

    const float* xcol = xs + tx * 4;
    const float* wrow = Ws + ty * 8;

#pragma unroll 8
    for (int k = 0; k < HID; ++k) {
        float4 xv = *reinterpret_cast<const float4*>(xcol + k * TBKP);
        ulonglong2 w01 = *reinterpret_cast<const ulonglong2*>(wrow + k * NEXP);
        ulonglong2 w23 = *reinterpret_cast<const ulonglong2*>(wrow + k * NEXP + 4);
        unsigned long long a0 = pack_dup(xv.x);
        unsigned long long a1 = pack_dup(xv.y);
        unsigned long long a2 = pack_dup(xv.z);
        unsigned long long a3 = pack_dup(xv.w);
        ffma2(acc[0][0], a0, w01.x); ffma2(acc[0][1], a0, w01.y);
        ffma2(acc[0][2], a0, w23.x); ffma2(acc[0][3], a0, w23.y);
        ffma2(acc[1][0], a1, w01.x); ffma2(acc[1][1], a1, w01.y);
        ffma2(acc[1][2], a1, w23.x); ffma2(acc[1][3], a1, w23.y);
        ffma2(acc[2][0], a2, w01.x); ffma2(acc[2][1], a2, w01.y);
        ffma2(acc[2][2], a2, w23.x); ffma2(acc[2][3], a2, w23.y);
        ffma2(acc[3][0], a3, w01.x); ffma2(acc[3][1], a3, w01.y);
        ffma2(acc[3][2], a3, w23.x); ffma2(acc[3][3], a3, w23.y);
    }
    __syncthreads();   // xs reads + Ws reads done

    // --- scatter logits to L [token][expert] ---
#pragma unroll
    for (int r = 0; r < 4; ++r) {
        int t = tx * 4 + r;
#pragma unroll
        for (int cp = 0; cp < 4; ++cp) {
            float lo, hi;
            unpack2(acc[r][cp], lo, hi);
            int e = ty * 8 + cp * 2;
            L[t * LPAD + e]     = lo;
            L[t * LPAD + e + 1] = hi;
        }
    }
    __syncthreads();

    // --- E1: pair-split local top-6 + local softmax (all 256 threads) ---
    {
        int t = tid & 127;
        int h = tid >> 7;                       // expert half 0/1
        float* lr = L + t * LPAD + h * 32;

        float v[32];
#pragma unroll
        for (int j = 0; j < 8; ++j) {
            float4 q = *reinterpret_cast<const float4*>(lr + 4 * j);
            v[4 * j]     = q.x;
            v[4 * j + 1] = q.y;
            v[4 * j + 2] = q.z;
            v[4 * j + 3] = q.w;
        }

        unsigned mask = 0;
        float tv[6]; int ti[6];
#pragma unroll
        for (int p = 0; p < 6; ++p) {
            float bv; int bi;
            argmax32(v, mask, bv, bi);
            mask |= 1u << bi;
            tv[p] = bv;
            ti[p] = bi;
        }

        float m = tv[0];
        float Z = 0.f;
#pragma unroll
        for (int j = 0; j < 32; ++j) {
            float e = __expf(v[j] - m);
            Z += e;
            v[j] = e;
        }
#pragma unroll
        for (int j = 0; j < 8; ++j) {
            *reinterpret_cast<float4*>(lr + 4 * j) =
                make_float4(v[4 * j], v[4 * j + 1], v[4 * j + 2], v[4 * j + 3]);
        }
#pragma unroll
        for (int p = 0; p < 6; ++p) {
            candV[t * 12 + h * 6 + p] = tv[p];
            candI[t * 12 + h * 6 + p] = ti[p] + h * 32;
        }
        mzA[t * 4 + h * 2]     = m;
        mzA[t * 4 + h * 2 + 1] = Z;
    }
    __syncthreads();

    // --- E2: merge halves, outputs (one thread per token) ---
    if (tid < TBK) {
        const int t = tid;
        float av[6], bv[6]; int ai6[6], bi6[6];
#pragma unroll
        for (int k = 0; k < 6; ++k) {
            av[k]  = candV[t * 12 + k];
            ai6[k] = candI[t * 12 + k];
            bv[k]  = candV[t * 12 + 6 + k];
            bi6[k] = candI[t * 12 + 6 + k];
        }
        float mA = mzA[t * 4 + 0], ZA = mzA[t * 4 + 1];
        float mB = mzA[t * 4 + 2], ZB = mzA[t * 4 + 3];

        float mv[6]; int mi[6];
#pragma unroll
        for (int k = 0; k < 6; ++k) {
            bool p = av[0] >= bv[0];          // tie -> half0 (lower expert)
            mv[k] = p ? av[0] : bv[0];
            mi[k] = p ? ai6[0] : bi6[0];
            if (p) {
                av[0]=av[1]; av[1]=av[2]; av[2]=av[3]; av[3]=av[4]; av[4]=av[5]; av[5]=NEGINF;
                ai6[0]=ai6[1]; ai6[1]=ai6[2]; ai6[2]=ai6[3]; ai6[3]=ai6[4]; ai6[4]=ai6[5];
            } else {
                bv[0]=bv[1]; bv[1]=bv[2]; bv[2]=bv[3]; bv[3]=bv[4]; bv[4]=bv[5]; bv[5]=NEGINF;
                bi6[0]=bi6[1]; bi6[1]=bi6[2]; bi6[2]=bi6[3]; bi6[3]=bi6[4]; bi6[4]=bi6[5];
            }
        }

        float m  = fmaxf(mA, mB);
        float eA = __expf(mA - m);
        float eB = __expf(mB - m);
        float Z  = ZA * eA + ZB * eB;
        float invZ = 1.f / Z;
        sc[2 * t]     = eA * invZ;
        sc[2 * t + 1] = eB * invZ;

        float ev[6]; float E6 = 0.f;
#pragma unroll
        for (int k = 0; k < 6; ++k) { ev[k] = __expf(mv[k] - m); E6 += ev[k]; }
        float invd = 1.f / (E6 + 1e-20f * Z);   // == ref renormalization exactly

        size_t gt = (size_t)blk * TBK + t;
        float* oi = out + gt * 6;
        float* ow = out + (size_t)N * 6 + gt * 6;
#pragma unroll
        for (int k = 0; k < 6; ++k) {
            oi[k] = (float)mi[k];
            ow[k] = ev[k] * invd;
            atomicAdd(&cntS[mi[k]], 1);
        }
    }
    __syncthreads();

    // --- E3: Pi column sums, 256 threads (4 partials per expert) ---
    {
        int e  = tid & 63;
        int q  = tid >> 6;
        int hh = e >> 5;
        float s0 = 0.f, s1 = 0.f, s2 = 0.f, s3 = 0.f;
#pragma unroll
        for (int j = 0; j < 32; j += 4) {
            int t0 = q * 32 + j;
            s0 = fmaf(L[(t0 + 0) * LPAD + e], sc[(t0 + 0) * 2 + hh], s0);
            s1 = fmaf(L[(t0 + 1) * LPAD + e], sc[(t0 + 1) * 2 + hh], s1);
            s2 = fmaf(L[(t0 + 2) * LPAD + e], sc[(t0 + 2) * 2 + hh], s2);
            s3 = fmaf(L[(t0 + 3) * LPAD + e], sc[(t0 + 3) * 2 + hh], s3);
        }
        part[q * 64 + e] = (s0 + s1) + (s2 + s3);
    }
    __syncthreads();

    // --- E4: one deterministic fixed-point atomic per expert per block ---
    if (tid < NEXP) {
        float s = ((part[tid] + part[64 + tid]) + (part[128 + tid] + part[192 + tid]));
        atomicAdd(&g_scoreFix[tid], (unsigned long long)(s * 1073741824.0f)); // *2^30
        atomicAdd(&g_cnt[tid], cntS[tid]);
    }
}

// ---- kernel 3: finalize aux loss ----
__global__ void moe_final(float* __restrict__ out, int N) {
    if (threadIdx.x == 0) {
        double aux  = 0.0;
        double invN = 1.0 / (double)N;
        for (int e = 0; e < NEXP; ++e) {
            double Pi = (double)g_scoreFix[e] * (1.0 / 1073741824.0) * invN;
            double fi = (double)g_cnt[e] * 64.0 / ((double)N * 6.0);
            aux += Pi * fi;
        }
        out[(size_t)N * 12] = (float)(aux * 1e-3);
    }
}

extern "C" void kernel_launch(void* const* d_in, const int* in_sizes, int n_in,
                              void* d_out, int out_size) {
    const float* x = (const float*)d_in[0];
    const float* W = (const float*)d_in[1];
    int N = in_sizes[0] / HID;

    int smem_bytes = (HID * TBKP + HID * NEXP + TBK * 2) * (int)sizeof(float)
                   + NEXP * (int)sizeof(int);
    cudaFuncSetAttribute(moe_main, cudaFuncAttributeMaxDynamicSharedMemorySize, smem_bytes);

    moe_prep<<<33, 256>>>(W);
    moe_main<<<N / TBK, NTHREADS, smem_bytes>>>(x, (float*)d_out, N);
    moe_final<<<1, 32>>>((float*)d_out, N);
}

// round 3
// speedup vs baseline: 1.3086x; 1.3086x over previous
#include <cuda_runtime.h>
#include <cstdint>

#define TBK      128   // tokens per block
#define NTHREADS 256
#define HID      128
#define NEXP     64
#define TBKP     132   // xs row stride (floats)
#define WSP      68    // Ws row stride (floats): 4-way transpose STS, 16B-aligned rows
#define LPAD     68    // logits row pad
#define NEGINF   (__int_as_float(0xff800000u))

// ---- device scratch (zero-initialized statics; last block self-resets) ----
__device__ unsigned long long g_scoreFix[NEXP];
__device__ int                g_cnt[NEXP];
__device__ int                g_sync;

// ---- f32x2 helpers ----
__device__ __forceinline__ unsigned long long pack_dup(float v) {
    unsigned long long r;
    unsigned int b = __float_as_uint(v);
    asm("mov.b64 %0, {%1, %1};" : "=l"(r) : "r"(b));
    return r;
}
__device__ __forceinline__ void ffma2(unsigned long long& d, unsigned long long a,
                                      unsigned long long b) {
    asm("fma.rn.f32x2 %0, %1, %2, %0;" : "+l"(d) : "l"(a), "l"(b));
}
__device__ __forceinline__ void unpack2(unsigned long long v, float& lo, float& hi) {
    unsigned int a, b;
    asm("mov.b64 {%0, %1}, %2;" : "=r"(a), "=r"(b) : "l"(v));
    lo = __uint_as_float(a);
    hi = __uint_as_float(b);
}

// ---- tournament argmax over 32 register values, exact lower-index tie-break ----
__device__ __forceinline__ void argmax32(const float (&v)[32], unsigned mask,
                                         float& bv, int& bi) {
    float a[16]; int ia[16];
#pragma unroll
    for (int i = 0; i < 16; ++i) {
        float x0 = (mask & (1u << (2 * i)))     ? NEGINF : v[2 * i];
        float x1 = (mask & (1u << (2 * i + 1))) ? NEGINF : v[2 * i + 1];
        bool p = x0 >= x1;
        a[i]  = p ? x0 : x1;
        ia[i] = p ? 2 * i : 2 * i + 1;
    }
    float b[8]; int ib[8];
#pragma unroll
    for (int i = 0; i < 8; ++i) {
        bool p = a[2 * i] >= a[2 * i + 1];
        b[i]  = p ? a[2 * i] : a[2 * i + 1];
        ib[i] = p ? ia[2 * i] : ia[2 * i + 1];
    }
    float c[4]; int ic[4];
#pragma unroll
    for (int i = 0; i < 4; ++i) {
        bool p = b[2 * i] >= b[2 * i + 1];
        c[i]  = p ? b[2 * i] : b[2 * i + 1];
        ic[i] = p ? ib[2 * i] : ib[2 * i + 1];
    }
    bool p0 = c[0] >= c[1];
    float d0 = p0 ? c[0] : c[1];  int id0 = p0 ? ic[0] : ic[1];
    bool p1 = c[2] >= c[3];
    float d1 = p1 ? c[2] : c[3];  int id1 = p1 ? ic[2] : ic[3];
    bool p = d0 >= d1;
    bv = p ? d0 : d1;
    bi = p ? id0 : id1;
}

extern __shared__ float smem[];

__global__ __launch_bounds__(NTHREADS, 2)
void moe_main(const float* __restrict__ x, const float* __restrict__ W,
              float* __restrict__ out, int N) {
    float* xs   = smem;                       // [HID][TBKP] (x transposed, col-swizzled)
    float* Ws   = smem + HID * TBKP;          // [HID][WSP]  (W k-major)
    float* sc   = Ws + HID * WSP;             // [TBK][2]    half-scales e^{mh-m}/Z
    int*   cntS = (int*)(sc + TBK * 2);       // [NEXP]
    int*   lastF = cntS + NEXP;               // [1] last-block flag
    float* L    = xs;                         // [TBK][LPAD] logits->exps (aliases xs)

    // aliases into Ws after GEMM reads complete:
    float* candV = Ws;                        // [TBK][12]
    int*   candI = (int*)(Ws + TBK * 12);     // [TBK][12]
    float* mzA   = Ws + TBK * 24;             // [TBK][4]: mA, ZA, mB, ZB
    float* part  = Ws + TBK * 28;             // [4][64] Pi partials
    double* dterm = (double*)(Ws + TBK * 28); // [64] finalize terms (same region, later)

    const int tid = threadIdx.x;
    const long long blk = blockIdx.x;
    const float* xblk = x + blk * (long long)(TBK * HID);

    // --- stage x transposed: coalesced LDG.128, XOR-swizzled STS (4-way) ---
    {
        const float4* gx = reinterpret_cast<const float4*>(xblk);
#pragma unroll
        for (int c = 0; c < 16; ++c) {
            int f = c * NTHREADS + tid;       // float4 index over [TBK][HID/4]
            float4 g = gx[f];
            int t    = f >> 5;                // token (same for whole warp round)
            int lane = f & 31;
            int k4   = lane * 4;              // hidden base; k>>2 == lane
            int colb = t ^ ((lane & 7) << 2); // swizzled column base
            xs[(k4 + 0) * TBKP + colb] = g.x;
            xs[(k4 + 1) * TBKP + colb] = g.y;
            xs[(k4 + 2) * TBKP + colb] = g.z;
            xs[(k4 + 3) * TBKP + colb] = g.w;
        }
    }
    // --- stage W transposed: coalesced LDG, 4-way STS (stride 68) ---
#pragma unroll
    for (int c = 0; c < 32; ++c) {
        int i = c * NTHREADS + tid;           // i = e*128 + k
        int e = i >> 7, k = i & 127;
        Ws[k * WSP + e] = W[i];
    }
    if (tid < NEXP) cntS[tid] = 0;
    __syncthreads();

    // --- GEMM: 4 tokens x 8 experts per thread, f32x2 over experts ---
    const int tx = tid & 31;
    const int ty = tid >> 5;
    unsigned long long acc[4][4];
#pragma unroll
    for (int r = 0; r < 4; ++r)
#pragma unroll
        for (int c = 0; c < 4; ++c) acc[r][c] = 0ull;

    const float* wrow = Ws + ty * 8;

#pragma unroll 8
    for (int k = 0; k < HID; ++k) {
        int col4 = (tx ^ ((k >> 2) & 7)) << 2;        // de-swizzle
        float4 xv = *reinterpret_cast<const float4*>(xs + k * TBKP + col4);
        ulonglong2 w01 = *reinterpret_cast<const ulonglong2*>(wrow + k * WSP);
        ulonglong2 w23 = *reinterpret_cast<const ulonglong2*>(wrow + k * WSP + 4);
        unsigned long long a0 = pack_dup(xv.x);
        unsigned long long a1 = pack_dup(xv.y);
        unsigned long long a2 = pack_dup(xv.z);
        unsigned long long a3 = pack_dup(xv.w);
        ffma2(acc[0][0], a0, w01.x); ffma2(acc[0][1], a0, w01.y);
        ffma2(acc[0][2], a0, w23.x); ffma2(acc[0][3], a0, w23.y);
        ffma2(acc[1][0], a1, w01.x); ffma2(acc[1][1], a1, w01.y);
        ffma2(acc[1][2], a1, w23.x); ffma2(acc[1][3], a1, w23.y);
        ffma2(acc[2][0], a2, w01.x); ffma2(acc[2][1], a2, w01.y);
        ffma2(acc[2][2], a2, w23.x); ffma2(acc[2][3], a2, w23.y);
        ffma2(acc[3][0], a3, w01.x); ffma2(acc[3][1], a3, w01.y);
        ffma2(acc[3][2], a3, w23.x); ffma2(acc[3][3], a3, w23.y);
    }
    __syncthreads();   // xs + Ws reads done

    // --- scatter logits to L [token][expert] (note: threads own tokens tx*4+r) ---
#pragma unroll
    for (int r = 0; r < 4; ++r) {
        int t = tx * 4 + r;
#pragma unroll
        for (int cp = 0; cp < 4; ++cp) {
            float lo, hi;
            unpack2(acc[r][cp], lo, hi);
            int e = ty * 8 + cp * 2;
            L[t * LPAD + e]     = lo;
            L[t * LPAD + e + 1] = hi;
        }
    }
    __syncthreads();

    // --- E1: pair-split local top-6 + local softmax (all 256 threads) ---
    {
        int t = tid & 127;
        int h = tid >> 7;
        float* lr = L + t * LPAD + h * 32;

        float v[32];
#pragma unroll
        for (int j = 0; j < 8; ++j) {
            float4 q = *reinterpret_cast<const float4*>(lr + 4 * j);
            v[4 * j] = q.x; v[4 * j + 1] = q.y; v[4 * j + 2] = q.z; v[4 * j + 3] = q.w;
        }

        unsigned mask = 0;
        float tv[6]; int ti[6];
#pragma unroll
        for (int p = 0; p < 6; ++p) {
            float bv; int bi;
            argmax32(v, mask, bv, bi);
            mask |= 1u << bi;
            tv[p] = bv; ti[p] = bi;
        }

        float m = tv[0];
        float Z = 0.f;
#pragma unroll
        for (int j = 0; j < 32; ++j) {
            float e = __expf(v[j] - m);
            Z += e;
            v[j] = e;
        }
#pragma unroll
        for (int j = 0; j < 8; ++j)
            *reinterpret_cast<float4*>(lr + 4 * j) =
                make_float4(v[4 * j], v[4 * j + 1], v[4 * j + 2], v[4 * j + 3]);
#pragma unroll
        for (int p = 0; p < 6; ++p) {
            candV[t * 12 + h * 6 + p] = tv[p];
            candI[t * 12 + h * 6 + p] = ti[p] + h * 32;
        }
        mzA[t * 4 + h * 2]     = m;
        mzA[t * 4 + h * 2 + 1] = Z;
    }
    __syncthreads();

    // --- E2: merge halves, emit outputs (one thread per token) ---
    if (tid < TBK) {
        const int t = tid;
        float av[6], bv[6]; int ai6[6], bi6[6];
#pragma unroll
        for (int k = 0; k < 6; ++k) {
            av[k]  = candV[t * 12 + k];      ai6[k] = candI[t * 12 + k];
            bv[k]  = candV[t * 12 + 6 + k];  bi6[k] = candI[t * 12 + 6 + k];
        }
        float mA = mzA[t * 4 + 0], ZA = mzA[t * 4 + 1];
        float mB = mzA[t * 4 + 2], ZB = mzA[t * 4 + 3];

        float mv[6]; int mi[6];
#pragma unroll
        for (int k = 0; k < 6; ++k) {
            bool p = av[0] >= bv[0];          // tie -> half0 (lower expert index)
            mv[k] = p ? av[0] : bv[0];
            mi[k] = p ? ai6[0] : bi6[0];
            if (p) {
                av[0]=av[1]; av[1]=av[2]; av[2]=av[3]; av[3]=av[4]; av[4]=av[5]; av[5]=NEGINF;
                ai6[0]=ai6[1]; ai6[1]=ai6[2]; ai6[2]=ai6[3]; ai6[3]=ai6[4]; ai6[4]=ai6[5];
            } else {
                bv[0]=bv[1]; bv[1]=bv[2]; bv[2]=bv[3]; bv[3]=bv[4]; bv[4]=bv[5]; bv[5]=NEGINF;
                bi6[0]=bi6[1]; bi6[1]=bi6[2]; bi6[2]=bi6[3]; bi6[3]=bi6[4]; bi6[4]=bi6[5];
            }
        }

        float m  = fmaxf(mA, mB);
        float eA = __expf(mA - m);
        float eB = __expf(mB - m);
        float Z  = ZA * eA + ZB * eB;
        float invZ = 1.f / Z;
        sc[2 * t]     = eA * invZ;
        sc[2 * t + 1] = eB * invZ;

        float ev[6]; float E6 = 0.f;
#pragma unroll
        for (int k = 0; k < 6; ++k) { ev[k] = __expf(mv[k] - m); E6 += ev[k]; }
        float invd = 1.f / (E6 + 1e-20f * Z);   // matches ref renormalization exactly

        size_t gt = (size_t)blk * TBK + t;
        float* oi = out + gt * 6;
        float* ow = out + (size_t)N * 6 + gt * 6;
#pragma unroll
        for (int k = 0; k < 6; ++k) {
            oi[k] = (float)mi[k];
            ow[k] = ev[k] * invd;
            atomicAdd(&cntS[mi[k]], 1);
        }
    }
    __syncthreads();

    // --- E3: Pi column sums (4 partials per expert) ---
    {
        int e  = tid & 63;
        int q  = tid >> 6;
        int hh = e >> 5;
        float s0 = 0.f, s1 = 0.f, s2 = 0.f, s3 = 0.f;
#pragma unroll
        for (int j = 0; j < 32; j += 4) {
            int t0 = q * 32 + j;
            s0 = fmaf(L[(t0 + 0) * LPAD + e], sc[(t0 + 0) * 2 + hh], s0);
            s1 = fmaf(L[(t0 + 1) * LPAD + e], sc[(t0 + 1) * 2 + hh], s1);
            s2 = fmaf(L[(t0 + 2) * LPAD + e], sc[(t0 + 2) * 2 + hh], s2);
            s3 = fmaf(L[(t0 + 3) * LPAD + e], sc[(t0 + 3) * 2 + hh], s3);
        }
        part[q * 64 + e] = (s0 + s1) + (s2 + s3);
    }
    __syncthreads();

    // --- E4: one deterministic fixed-point atomic per expert per block ---
    if (tid < NEXP) {
        float s = ((part[tid] + part[64 + tid]) + (part[128 + tid] + part[192 + tid]));
        atomicAdd(&g_scoreFix[tid], (unsigned long long)(s * 1073741824.0f)); // *2^30
        atomicAdd(&g_cnt[tid], cntS[tid]);
    }
    __syncthreads();

    // --- last-block finalize: aux loss + self-reset of accumulators ---
    if (tid == 0) {
        __threadfence();
        int r = atomicAdd(&g_sync, 1);
        lastF[0] = (r == (int)gridDim.x - 1) ? 1 : 0;
    }
    __syncthreads();
    if (lastF[0]) {
        __threadfence();
        if (tid < NEXP) {
            double invN = 1.0 / (double)N;
            double Pi = (double)g_scoreFix[tid] * (1.0 / 1073741824.0) * invN;
            double fi = (double)g_cnt[tid] * 64.0 / ((double)N * 6.0);
            dterm[tid] = Pi * fi;
            g_scoreFix[tid] = 0ull;           // reset for next call (graph replay)
            g_cnt[tid]      = 0;
        }
        __syncthreads();
        if (tid == 0) {
            double aux = 0.0;
            for (int e = 0; e < NEXP; ++e) aux += dterm[e];
            out[(size_t)N * 12] = (float)(aux * 1e-3);
            g_sync = 0;                       // reset counter
        }
    }
}

extern "C" void kernel_launch(void* const* d_in, const int* in_sizes, int n_in,
                              void* d_out, int out_size) {
    const float* x = (const float*)d_in[0];
    const float* W = (const float*)d_in[1];
    int N = in_sizes[0] / HID;

    int smem_bytes = (HID * TBKP + HID * WSP + TBK * 2) * (int)sizeof(float)
                   + (NEXP + 1) * (int)sizeof(int);
    cudaFuncSetAttribute(moe_main, cudaFuncAttributeMaxDynamicSharedMemorySize, smem_bytes);

    moe_main<<<N / TBK, NTHREADS, smem_bytes>>>(x, W, (float*)d_out, N);
}